// round 15
// baseline (speedup 1.0000x reference)
#include <cuda_runtime.h>
#include <cuda_fp16.h>

#define N_NODES 100000
#define N_EDGES 1600000
#define F_HID 64
#define NCHUNK ((N_NODES + 1023) / 1024)
#define NPART 12500                       // agg1 grid (= N_NODES/8 warps)
#define FULLM 0xffffffffu

// ---------------- scratch (static device globals) ----------------
__device__ int    g_is64;
__device__ int    g_cnt[N_NODES];
__device__ int    g_rowstart[N_NODES];
__device__ int    g_cursor[N_NODES];
__device__ int    g_col[N_EDGES];
__device__ int    g_bsum[NCHUNK];
__device__ float  g_dinv[N_NODES];
__device__ float  g_w[N_NODES];           // sum over out-edges of dinv[dst]
__device__ unsigned char g_xs8[(size_t)N_NODES * F_HID];  // e4m3 dinv*(x@W1)
__device__ float  g_partial[F_HID * NPART];
__device__ float  g_v[F_HID];

__device__ __forceinline__ float tf32r(float f) {
    asm("cvt.rna.tf32.f32 %0, %0;" : "+f"(f));
    return f;
}
// pack: hi -> high byte, lo -> low byte
__device__ __forceinline__ unsigned short pack_e4m3(float hi, float lo) {
    unsigned short r;
    asm("cvt.rn.satfinite.e4m3x2.f32 %0, %1, %2;" : "=h"(r) : "f"(hi), "f"(lo));
    return r;
}
// unpack: low byte -> .x, high byte -> .y
__device__ __forceinline__ __half2 unpack_e4m3(unsigned short v) {
    unsigned int r;
    asm("cvt.rn.f16x2.e4m3x2 %0, %1;" : "=r"(r) : "h"(v));
    return *(__half2*)&r;
}

// ---------------- zero + dtype sniff (block 0) ----------------
__global__ void k_zero(const unsigned int* __restrict__ e) {
    int i = blockIdx.x * blockDim.x + threadIdx.x;
    if (i < N_NODES) { g_cnt[i] = 0; g_w[i] = 0.f; }
    if (blockIdx.x == 0 && threadIdx.x < 32) {
        unsigned int acc = 0;
        for (int k = threadIdx.x; k < 2048; k += 32)
            if (k & 1) acc |= e[k];
        #pragma unroll
        for (int o = 16; o; o >>= 1) acc |= __shfl_xor_sync(FULLM, acc, o);
        if (threadIdx.x == 0) g_is64 = (acc == 0u) ? 1 : 0;
    }
}

// ---------------- degree count over dst (low-word reads) ----------------
__global__ void k_count(const void* __restrict__ eiv) {
    int e = blockIdx.x * blockDim.x + threadIdx.x;
    if (e >= N_EDGES) return;
    const int* ei = (const int*)eiv;
    int d;
    if (g_is64) d = ei[2 * ((size_t)N_EDGES + e)];   // little-endian low word
    else        d = ei[(size_t)N_EDGES + e];
    atomicAdd(&g_cnt[d], 1);
}

// ---------------- exclusive scan, block partials ----------------
__global__ void k_scan_partial() {
    __shared__ int wsum[8];
    int t = threadIdx.x;
    int lane = t & 31, w = t >> 5;
    int gi = blockIdx.x * 256 + t;
    int4 v = make_int4(0, 0, 0, 0);
    if (gi < N_NODES / 4) v = ((const int4*)g_cnt)[gi];
    int p0 = v.x, p1 = p0 + v.y, p2 = p1 + v.z, p3 = p2 + v.w;
    int tsum = p3;
    int incl = tsum;
    #pragma unroll
    for (int o = 1; o < 32; o <<= 1) {
        int n = __shfl_up_sync(FULLM, incl, o);
        if (lane >= o) incl += n;
    }
    if (lane == 31) wsum[w] = incl;
    __syncthreads();
    if (w == 0) {
        int s = (lane < 8) ? wsum[lane] : 0;
        #pragma unroll
        for (int o = 1; o < 8; o <<= 1) {
            int n = __shfl_up_sync(FULLM, s, o);
            if (lane >= o) s += n;
        }
        if (lane < 8) wsum[lane] = s;
    }
    __syncthreads();
    int base = (w > 0 ? wsum[w - 1] : 0) + (incl - tsum);
    if (gi < N_NODES / 4)
        ((int4*)g_rowstart)[gi] = make_int4(base, base + p0, base + p1, base + p2);
    if (t == 0) g_bsum[blockIdx.x] = wsum[7];
}

// ---------------- scan finalize: in-block chunk-prefix ----------------
__global__ void k_scan_add() {
    __shared__ int pref;
    int c = blockIdx.x >> 2;              // chunk id: 1024 nodes/chunk
    int t = threadIdx.x;
    if (t < 32) {
        int s = 0;
        for (int j = t; j < NCHUNK; j += 32)
            if (j < c) s += g_bsum[j];
        #pragma unroll
        for (int o = 16; o; o >>= 1) s += __shfl_xor_sync(FULLM, s, o);
        if (t == 0) pref = s;
    }
    __syncthreads();
    int i = blockIdx.x * 256 + t;
    if (i < N_NODES) {
        int rs = g_rowstart[i] + pref;
        g_rowstart[i] = rs;
        g_cursor[i]   = rs;
        g_dinv[i] = rsqrtf((float)(g_cnt[i] + 1));
    }
}

// ---------------- CSR placement + w scatter (low-word reads) -------------
__global__ void k_place(const void* __restrict__ eiv) {
    int e = blockIdx.x * blockDim.x + threadIdx.x;
    if (e >= N_EDGES) return;
    const int* ei = (const int*)eiv;
    int s, d;
    if (g_is64) {
        s = ei[2 * (size_t)e];
        d = ei[2 * ((size_t)N_EDGES + e)];
    } else {
        s = ei[(size_t)e];
        d = ei[(size_t)N_EDGES + e];
    }
    int pos = atomicAdd(&g_cursor[d], 1);
    g_col[pos] = s;
    atomicAdd(&g_w[s], g_dinv[d]);
}

// ---------------- GEMM1: xs8 = e4m3(dinv*(x@W1)) via tf32 mma.sync -------
// block tile 64 rows x 64 cols; 8 warps = 4 row-strips x 2 n-halves.
__global__ void __launch_bounds__(256) k_gemm1(const float* __restrict__ x,
                                               const float* __restrict__ W1) {
    __shared__ float WsT[64][68];   // [n][k], tf32-rounded, padded
    __shared__ float Xs[64][68];    // [row][k], tf32-rounded, padded
    int t = threadIdx.x;
    int lane = t & 31, warp = t >> 5;
    int rs = warp & 3;              // row strip
    int nh = warp >> 2;             // n half
    int g = lane >> 2, tig = lane & 3;
    for (int i = t; i < 1024; i += 256) {
        int k = i >> 4, n4 = (i & 15) * 4;
        float4 wv = *(const float4*)(W1 + k * 64 + n4);
        WsT[n4 + 0][k] = tf32r(wv.x);
        WsT[n4 + 1][k] = tf32r(wv.y);
        WsT[n4 + 2][k] = tf32r(wv.z);
        WsT[n4 + 3][k] = tf32r(wv.w);
    }
    int ntiles = (N_NODES + 63) / 64;
    for (int tile = blockIdx.x; tile < ntiles; tile += gridDim.x) {
        int row0 = tile * 64;
        __syncthreads();
        for (int i = t; i < 1024; i += 256) {
            int rr = i >> 4, q = i & 15;
            int grow = row0 + rr;
            float4 v = make_float4(0.f, 0.f, 0.f, 0.f);
            if (grow < N_NODES) v = *(const float4*)(x + (size_t)grow * 64 + 4 * q);
            Xs[rr][4 * q + 0] = tf32r(v.x);
            Xs[rr][4 * q + 1] = tf32r(v.y);
            Xs[rr][4 * q + 2] = tf32r(v.z);
            Xs[rr][4 * q + 3] = tf32r(v.w);
        }
        __syncthreads();
        float acc[4][4] = {};
        #pragma unroll
        for (int k0 = 0; k0 < 8; k0++) {
            int kk = 8 * k0;
            unsigned int a0 = __float_as_uint(Xs[16 * rs + g][kk + tig]);
            unsigned int a1 = __float_as_uint(Xs[16 * rs + g + 8][kk + tig]);
            unsigned int a2 = __float_as_uint(Xs[16 * rs + g][kk + tig + 4]);
            unsigned int a3 = __float_as_uint(Xs[16 * rs + g + 8][kk + tig + 4]);
            #pragma unroll
            for (int n0 = 0; n0 < 4; n0++) {
                int nn = 32 * nh + 8 * n0;
                unsigned int b0 = __float_as_uint(WsT[nn + g][kk + tig]);
                unsigned int b1 = __float_as_uint(WsT[nn + g][kk + tig + 4]);
                asm("mma.sync.aligned.m16n8k8.row.col.f32.tf32.tf32.f32 "
                    "{%0,%1,%2,%3}, {%4,%5,%6,%7}, {%8,%9}, {%0,%1,%2,%3};"
                    : "+f"(acc[n0][0]), "+f"(acc[n0][1]),
                      "+f"(acc[n0][2]), "+f"(acc[n0][3])
                    : "r"(a0), "r"(a1), "r"(a2), "r"(a3), "r"(b0), "r"(b1));
            }
        }
        int rowA = row0 + 16 * rs + g;
        int rowB = rowA + 8;
        float da = (rowA < N_NODES) ? g_dinv[rowA] : 0.f;
        float db = (rowB < N_NODES) ? g_dinv[rowB] : 0.f;
        #pragma unroll
        for (int n0 = 0; n0 < 4; n0++) {
            int nn = 32 * nh + 8 * n0 + 2 * tig;
            if (rowA < N_NODES)
                *(unsigned short*)(g_xs8 + (size_t)rowA * 64 + nn) =
                    pack_e4m3(da * acc[n0][1], da * acc[n0][0]);  // hi=col nn+1, lo=col nn
            if (rowB < N_NODES)
                *(unsigned short*)(g_xs8 + (size_t)rowB * 64 + nn) =
                    pack_e4m3(db * acc[n0][3], db * acc[n0][2]);
        }
    }
}

// ---------------- fused agg1: fp8 gather, 2 neighbors/iter, half2 accum --
// lane = (parity, feature-quad): half = lane>>4 picks even/odd neighbor,
// fl = lane&15 picks features 4*fl..4*fl+3 (one uint = 4 fp8).
__global__ void __launch_bounds__(256) k_agg1(const float* __restrict__ b1) {
    __shared__ float sp[8][64];
    int t = threadIdx.x;
    int warp = t >> 5, lane = t & 31;
    int gw = blockIdx.x * 8 + warp;       // all gw < N_NODES
    const unsigned int* xs4 = (const unsigned int*)g_xs8;   // 16 uint per row
    int start = g_rowstart[gw];
    int cnt   = g_cnt[gw];
    int half  = lane >> 4;
    int fl    = lane & 15;
    __half2 acc0 = __float2half2_rn(0.f), acc1 = acc0;
    if (half == 0) {                       // self loop into even-partial
        unsigned int s = xs4[(size_t)gw * 16 + fl];
        acc0 = unpack_e4m3((unsigned short)(s & 0xffffu));
        acc1 = unpack_e4m3((unsigned short)(s >> 16));
    }
    for (int base = 0; base < cnt; base += 32) {
        int idx = base + lane;
        int jreg = (idx < cnt) ? g_col[start + idx] : 0;
        int m = min(32, cnt - base);
        int kp = 0;
        for (; kp + 8 <= m; kp += 8) {
            int j0 = __shfl_sync(FULLM, jreg, kp     + half);
            int j1 = __shfl_sync(FULLM, jreg, kp + 2 + half);
            int j2 = __shfl_sync(FULLM, jreg, kp + 4 + half);
            int j3 = __shfl_sync(FULLM, jreg, kp + 6 + half);
            unsigned int v0 = __ldg(&xs4[(size_t)j0 * 16 + fl]);
            unsigned int v1 = __ldg(&xs4[(size_t)j1 * 16 + fl]);
            unsigned int v2 = __ldg(&xs4[(size_t)j2 * 16 + fl]);
            unsigned int v3 = __ldg(&xs4[(size_t)j3 * 16 + fl]);
            acc0 = __hadd2(acc0, __hadd2(
                       __hadd2(unpack_e4m3((unsigned short)(v0 & 0xffffu)),
                               unpack_e4m3((unsigned short)(v1 & 0xffffu))),
                       __hadd2(unpack_e4m3((unsigned short)(v2 & 0xffffu)),
                               unpack_e4m3((unsigned short)(v3 & 0xffffu)))));
            acc1 = __hadd2(acc1, __hadd2(
                       __hadd2(unpack_e4m3((unsigned short)(v0 >> 16)),
                               unpack_e4m3((unsigned short)(v1 >> 16))),
                       __hadd2(unpack_e4m3((unsigned short)(v2 >> 16)),
                               unpack_e4m3((unsigned short)(v3 >> 16)))));
        }
        for (; kp + 2 <= m; kp += 2) {
            int j = __shfl_sync(FULLM, jreg, kp + half);
            unsigned int v = __ldg(&xs4[(size_t)j * 16 + fl]);
            acc0 = __hadd2(acc0, unpack_e4m3((unsigned short)(v & 0xffffu)));
            acc1 = __hadd2(acc1, unpack_e4m3((unsigned short)(v >> 16)));
        }
        if (kp < m) {                      // odd tail: even-group only
            int j = __shfl_sync(FULLM, jreg, kp);
            if (half == 0) {
                unsigned int v = __ldg(&xs4[(size_t)j * 16 + fl]);
                acc0 = __hadd2(acc0, unpack_e4m3((unsigned short)(v & 0xffffu)));
                acc1 = __hadd2(acc1, unpack_e4m3((unsigned short)(v >> 16)));
            }
        }
    }
    unsigned int u0 = *(unsigned int*)&acc0;
    unsigned int u1 = *(unsigned int*)&acc1;
    unsigned int p0 = __shfl_xor_sync(FULLM, u0, 16);
    unsigned int p1 = __shfl_xor_sync(FULLM, u1, 16);
    acc0 = __hadd2(acc0, *(__half2*)&p0);
    acc1 = __hadd2(acc1, *(__half2*)&p1);
    if (half == 0) {
        float2 f01 = __half22float2(acc0);
        float2 f23 = __half22float2(acc1);
        float di = g_dinv[gw];
        float coef = di * (di + g_w[gw]);
        int f = 4 * fl;
        float4 o;
        o.x = coef * fmaxf(fmaf(di, f01.x, b1[f]),     0.f);
        o.y = coef * fmaxf(fmaf(di, f01.y, b1[f + 1]), 0.f);
        o.z = coef * fmaxf(fmaf(di, f23.x, b1[f + 2]), 0.f);
        o.w = coef * fmaxf(fmaf(di, f23.y, b1[f + 3]), 0.f);
        *(float4*)&sp[warp][f] = o;
    }
    __syncthreads();
    if (t < 64) {
        float s = 0.f;
        #pragma unroll
        for (int w = 0; w < 8; w++) s += sp[w][t];
        g_partial[(size_t)t * NPART + blockIdx.x] = s;
    }
}

// ---------------- reduce partials ----------------
__global__ void k_vred() {
    __shared__ float sh[8];
    int f = blockIdx.x, t = threadIdx.x;
    int lane = t & 31, w = t >> 5;
    float s = 0.f;
    for (int i = t; i < NPART; i += 256) s += g_partial[(size_t)f * NPART + i];
    #pragma unroll
    for (int o = 16; o; o >>= 1) s += __shfl_xor_sync(FULLM, s, o);
    if (lane == 0) sh[w] = s;
    __syncthreads();
    if (t == 0) {
        float tot = 0.f;
        #pragma unroll
        for (int i = 0; i < 8; i++) tot += sh[i];
        g_v[f] = tot;
    }
}

// ---------------- final: pooled = v@W2/N + b2, log_softmax ----------------
__global__ void k_fin(const float* __restrict__ W2, const float* __restrict__ b2,
                      float* __restrict__ out) {
    int c = threadIdx.x;
    float acc = 0.f;
    #pragma unroll
    for (int k = 0; k < 64; k++)
        acc = fmaf(g_v[k], __ldg(&W2[k * 32 + c]), acc);
    float p = acc * (1.0f / (float)N_NODES) + b2[c];
    float m = p;
    #pragma unroll
    for (int o = 16; o; o >>= 1) m = fmaxf(m, __shfl_xor_sync(FULLM, m, o));
    float e = expf(p - m);
    float s = e;
    #pragma unroll
    for (int o = 16; o; o >>= 1) s += __shfl_xor_sync(FULLM, s, o);
    out[c] = p - m - logf(s);
}

// ---------------- launcher ----------------
extern "C" void kernel_launch(void* const* d_in, const int* in_sizes, int n_in,
                              void* d_out, int out_size) {
    const float* x  = (const float*)d_in[0];
    const void*  ei = d_in[1];
    const float* W1 = (const float*)d_in[2];
    const float* b1 = (const float*)d_in[3];
    const float* W2 = (const float*)d_in[4];
    const float* b2 = (const float*)d_in[5];
    float*       out = (float*)d_out;

    k_zero<<<(N_NODES + 255) / 256, 256>>>((const unsigned int*)ei);
    k_count<<<(N_EDGES + 255) / 256, 256>>>(ei);
    k_scan_partial<<<NCHUNK, 256>>>();
    k_scan_add<<<(N_NODES + 255) / 256, 256>>>();
    k_place<<<(N_EDGES + 255) / 256, 256>>>(ei);

    k_gemm1<<<(N_NODES + 63) / 64, 256>>>(x, W1);
    k_agg1<<<NPART, 256>>>(b1);
    k_vred<<<F_HID, 256>>>();
    k_fin<<<1, 32>>>(W2, b2, out);
}